// round 3
// baseline (speedup 1.0000x reference)
#include <cuda_runtime.h>
#include <math.h>

// Problem constants
#define BB   128
#define LL   512
#define INPD 512
#define MEM  1024
#define MDIM (BB * LL)     // 65536
#define NDIM (2 * MEM)     // 2048
#define KDIM INPD          // 512

#define SOMA_FAST 4.0f
#define SOMA_SLOW 7.0f
#define MOD_BIAS  0.4f
#define EPS_BASE  0.9f
#define BIAS_MOD_RANGE 5.0f

// Scratch for soma_bias ([B, L, MEM] fp32 = 256 MiB). Static __device__ array
// (no allocation in kernel_launch).
__device__ float g_sb[(size_t)BB * LL * MEM];

// ---------------------------------------------------------------------------
// SGEMM: C[m,n] = sum_k A[m,k] * W[n,k] + bias[n]
//   A = u   viewed as [MDIM, KDIM] row-major
//   W = W_im            [NDIM, KDIM] row-major
// Epilogue: n <  MEM  -> g_sb[m*MEM + n]        = 5 * tanh(c/5)
//           n >= MEM  -> out [m*MEM + (n-MEM)]  = c          (io, in-place in d_out h_t region)
// Tile: 128x128x16, 256 threads, 8x8 per thread.
// ---------------------------------------------------------------------------
#define BM 128
#define BN 128
#define BK 16
#define TM 8
#define TN 8

__global__ __launch_bounds__(256, 2)
void gemm_epilogue_kernel(const float* __restrict__ A,
                          const float* __restrict__ W,
                          const float* __restrict__ bias,
                          float* __restrict__ out)
{
    __shared__ float As[BK][BM];
    __shared__ float Bs[BK][BN];

    const int n0  = blockIdx.x * BN;
    const int m0  = blockIdx.y * BM;
    const int tid = threadIdx.x;

    const int tx = tid & 15;   // 0..15 -> n direction
    const int ty = tid >> 4;   // 0..15 -> m direction

    // loader indices: each thread loads one float4 (4 consecutive k) per 64 rows
    const int lrow = tid >> 2;         // 0..63
    const int lcol = (tid & 3) << 2;   // 0,4,8,12

    float acc[TM][TN];
#pragma unroll
    for (int i = 0; i < TM; i++)
#pragma unroll
        for (int j = 0; j < TN; j++)
            acc[i][j] = 0.0f;

    for (int k0 = 0; k0 < KDIM; k0 += BK) {
        // Load A tile (transpose into As[k][m]) and W tile (into Bs[k][n])
#pragma unroll
        for (int r = 0; r < BM; r += 64) {
            float4 va = *(const float4*)&A[(size_t)(m0 + lrow + r) * KDIM + k0 + lcol];
            As[lcol + 0][lrow + r] = va.x;
            As[lcol + 1][lrow + r] = va.y;
            As[lcol + 2][lrow + r] = va.z;
            As[lcol + 3][lrow + r] = va.w;
            float4 vb = *(const float4*)&W[(size_t)(n0 + lrow + r) * KDIM + k0 + lcol];
            Bs[lcol + 0][lrow + r] = vb.x;
            Bs[lcol + 1][lrow + r] = vb.y;
            Bs[lcol + 2][lrow + r] = vb.z;
            Bs[lcol + 3][lrow + r] = vb.w;
        }
        __syncthreads();

#pragma unroll
        for (int k = 0; k < BK; k++) {
            float a[TM], b[TN];
            float4 a0 = *(const float4*)&As[k][ty * TM + 0];
            float4 a1 = *(const float4*)&As[k][ty * TM + 4];
            a[0] = a0.x; a[1] = a0.y; a[2] = a0.z; a[3] = a0.w;
            a[4] = a1.x; a[5] = a1.y; a[6] = a1.z; a[7] = a1.w;
            float4 b0 = *(const float4*)&Bs[k][tx * TN + 0];
            float4 b1 = *(const float4*)&Bs[k][tx * TN + 4];
            b[0] = b0.x; b[1] = b0.y; b[2] = b0.z; b[3] = b0.w;
            b[4] = b1.x; b[5] = b1.y; b[6] = b1.z; b[7] = b1.w;
#pragma unroll
            for (int i = 0; i < TM; i++)
#pragma unroll
                for (int j = 0; j < TN; j++)
                    acc[i][j] = fmaf(a[i], b[j], acc[i][j]);
        }
        __syncthreads();
    }

    // Epilogue. Entire block is either sb-half (n0 < MEM) or io-half.
    float bv[TN];
#pragma unroll
    for (int j = 0; j < TN; j++)
        bv[j] = bias[n0 + tx * TN + j];

    const bool is_sb = (n0 < MEM);
#pragma unroll
    for (int i = 0; i < TM; i++) {
        const int m = m0 + ty * TM + i;
#pragma unroll
        for (int j = 0; j < TN; j++) {
            const int n = n0 + tx * TN + j;
            float c = acc[i][j] + bv[j];
            if (is_sb) {
                g_sb[(size_t)m * MEM + n] =
                    BIAS_MOD_RANGE * tanhf(c * (1.0f / BIAS_MOD_RANGE));
            } else {
                out[(size_t)m * MEM + (n - MEM)] = c;
            }
        }
    }
}

// ---------------------------------------------------------------------------
// Scan: one thread per (b, m) state lane; 512 sequential timesteps.
// io lives in out[] (h_t region) and is overwritten in-place with hf.
// ---------------------------------------------------------------------------
__global__ __launch_bounds__(256)
void scan_kernel(const float* __restrict__ h0,
                 float* __restrict__ out)
{
    const int idx = blockIdx.x * blockDim.x + threadIdx.x;  // 0 .. B*MEM-1
    const int b = idx >> 10;        // / MEM
    const int m = idx & (MEM - 1);  // % MEM

    float hf = h0[(size_t)b * MEM + m];
    float hs = h0[(size_t)BB * MEM + (size_t)b * MEM + m];

    const size_t base = (size_t)b * LL * MEM + m;
    const float* __restrict__ sbp = g_sb + base;
    float* __restrict__ op = out + base;

#pragma unroll 4
    for (int t = 0; t < LL; t++) {
        const size_t off = (size_t)t * MEM;
        float sb = sbp[off];
        float io = op[off];

        float d  = hs + MOD_BIAS;
        float arg = io + SOMA_FAST * hf - SOMA_SLOW * d * d + sb;
        float hfn = tanhf(arg);

        float sg  = 1.0f / (1.0f + expf(-10.0f * (hf - 0.5f)));
        float eps = EPS_BASE + EPS_BASE * sg;
        hs = (1.0f - eps) * hs + eps * hf;
        hf = hfn;

        op[off] = hfn;
    }

    // hf_last appended after h_t
    out[(size_t)MDIM * MEM + (size_t)b * MEM + m] = hf;
}

// ---------------------------------------------------------------------------
// Launch
// inputs: d_in[0]=u [128,512,512] f32, d_in[1]=h0 [2,128,1024] f32,
//         d_in[2]=W_im [2048,512] f32, d_in[3]=b_im [2048] f32
// output: h_t [128,512,1024] f32 followed by hf_last [128,1024] f32
// ---------------------------------------------------------------------------
extern "C" void kernel_launch(void* const* d_in, const int* in_sizes, int n_in,
                              void* d_out, int out_size)
{
    const float* u    = (const float*)d_in[0];
    const float* h0   = (const float*)d_in[1];
    const float* W_im = (const float*)d_in[2];
    const float* b_im = (const float*)d_in[3];
    float* out = (float*)d_out;

    dim3 ggrid(NDIM / BN, MDIM / BM);  // (16, 512)
    gemm_epilogue_kernel<<<ggrid, 256>>>(u, W_im, b_im, out);

    scan_kernel<<<(BB * MEM) / 256, 256>>>(h0, out);
}

// round 5
// speedup vs baseline: 1.0023x; 1.0023x over previous
#include <cuda_runtime.h>
#include <math.h>

// Problem constants
#define BB   128
#define LL   512
#define INPD 512
#define MEM  1024
#define MDIM (BB * LL)     // 65536
#define NDIM (2 * MEM)     // 2048
#define KDIM INPD          // 512

#define SOMA_FAST 4.0f
#define SOMA_SLOW 7.0f
#define MOD_BIAS  0.4f
#define EPS_BASE  0.9f
#define BIAS_MOD_RANGE 5.0f

// Scratch for soma_bias ([B, L, MEM] fp32 = 256 MiB). Static __device__ array
// (no allocation in kernel_launch).
__device__ float g_sb[(size_t)BB * LL * MEM];

// ---------------------------------------------------------------------------
// SGEMM: C[m,n] = sum_k A[m,k] * W[n,k] + bias[n]
//   A = u   viewed as [MDIM, KDIM] row-major
//   W = W_im            [NDIM, KDIM] row-major
// Epilogue: n <  MEM  -> g_sb[m*MEM + n]        = 5 * tanh(c/5)
//           n >= MEM  -> out [m*MEM + (n-MEM)]  = c          (io, in-place in d_out h_t region)
// Tile: 128x128x16, 256 threads, 8x8 per thread.
// ---------------------------------------------------------------------------
#define BM 128
#define BN 128
#define BK 16
#define TM 8
#define TN 8

__global__ __launch_bounds__(256, 2)
void gemm_epilogue_kernel(const float* __restrict__ A,
                          const float* __restrict__ W,
                          const float* __restrict__ bias,
                          float* __restrict__ out)
{
    __shared__ float As[BK][BM];
    __shared__ float Bs[BK][BN];

    const int n0  = blockIdx.x * BN;
    const int m0  = blockIdx.y * BM;
    const int tid = threadIdx.x;

    const int tx = tid & 15;   // 0..15 -> n direction
    const int ty = tid >> 4;   // 0..15 -> m direction

    // loader indices: each thread loads one float4 (4 consecutive k) per 64 rows
    const int lrow = tid >> 2;         // 0..63
    const int lcol = (tid & 3) << 2;   // 0,4,8,12

    float acc[TM][TN];
#pragma unroll
    for (int i = 0; i < TM; i++)
#pragma unroll
        for (int j = 0; j < TN; j++)
            acc[i][j] = 0.0f;

    for (int k0 = 0; k0 < KDIM; k0 += BK) {
        // Load A tile (transpose into As[k][m]) and W tile (into Bs[k][n])
#pragma unroll
        for (int r = 0; r < BM; r += 64) {
            float4 va = *(const float4*)&A[(size_t)(m0 + lrow + r) * KDIM + k0 + lcol];
            As[lcol + 0][lrow + r] = va.x;
            As[lcol + 1][lrow + r] = va.y;
            As[lcol + 2][lrow + r] = va.z;
            As[lcol + 3][lrow + r] = va.w;
            float4 vb = *(const float4*)&W[(size_t)(n0 + lrow + r) * KDIM + k0 + lcol];
            Bs[lcol + 0][lrow + r] = vb.x;
            Bs[lcol + 1][lrow + r] = vb.y;
            Bs[lcol + 2][lrow + r] = vb.z;
            Bs[lcol + 3][lrow + r] = vb.w;
        }
        __syncthreads();

#pragma unroll
        for (int k = 0; k < BK; k++) {
            float a[TM], b[TN];
            float4 a0 = *(const float4*)&As[k][ty * TM + 0];
            float4 a1 = *(const float4*)&As[k][ty * TM + 4];
            a[0] = a0.x; a[1] = a0.y; a[2] = a0.z; a[3] = a0.w;
            a[4] = a1.x; a[5] = a1.y; a[6] = a1.z; a[7] = a1.w;
            float4 b0 = *(const float4*)&Bs[k][tx * TN + 0];
            float4 b1 = *(const float4*)&Bs[k][tx * TN + 4];
            b[0] = b0.x; b[1] = b0.y; b[2] = b0.z; b[3] = b0.w;
            b[4] = b1.x; b[5] = b1.y; b[6] = b1.z; b[7] = b1.w;
#pragma unroll
            for (int i = 0; i < TM; i++)
#pragma unroll
                for (int j = 0; j < TN; j++)
                    acc[i][j] = fmaf(a[i], b[j], acc[i][j]);
        }
        __syncthreads();
    }

    // Epilogue. Entire block is either sb-half (n0 < MEM) or io-half.
    float bv[TN];
#pragma unroll
    for (int j = 0; j < TN; j++)
        bv[j] = bias[n0 + tx * TN + j];

    const bool is_sb = (n0 < MEM);
#pragma unroll
    for (int i = 0; i < TM; i++) {
        const int m = m0 + ty * TM + i;
#pragma unroll
        for (int j = 0; j < TN; j++) {
            const int n = n0 + tx * TN + j;
            float c = acc[i][j] + bv[j];
            if (is_sb) {
                g_sb[(size_t)m * MEM + n] =
                    BIAS_MOD_RANGE * tanhf(c * (1.0f / BIAS_MOD_RANGE));
            } else {
                out[(size_t)m * MEM + (n - MEM)] = c;
            }
        }
    }
}

// ---------------------------------------------------------------------------
// Scan: one thread per (b, m) state lane; 512 sequential timesteps.
// io lives in out[] (h_t region) and is overwritten in-place with hf.
// ---------------------------------------------------------------------------
__global__ __launch_bounds__(256)
void scan_kernel(const float* __restrict__ h0,
                 float* __restrict__ out)
{
    const int idx = blockIdx.x * blockDim.x + threadIdx.x;  // 0 .. B*MEM-1
    const int b = idx >> 10;        // / MEM
    const int m = idx & (MEM - 1);  // % MEM

    float hf = h0[(size_t)b * MEM + m];
    float hs = h0[(size_t)BB * MEM + (size_t)b * MEM + m];

    const size_t base = (size_t)b * LL * MEM + m;
    const float* __restrict__ sbp = g_sb + base;
    float* __restrict__ op = out + base;

#pragma unroll 4
    for (int t = 0; t < LL; t++) {
        const size_t off = (size_t)t * MEM;
        float sb = sbp[off];
        float io = op[off];

        float d  = hs + MOD_BIAS;
        float arg = io + SOMA_FAST * hf - SOMA_SLOW * d * d + sb;
        float hfn = tanhf(arg);

        float sg  = 1.0f / (1.0f + expf(-10.0f * (hf - 0.5f)));
        float eps = EPS_BASE + EPS_BASE * sg;
        hs = (1.0f - eps) * hs + eps * hf;
        hf = hfn;

        op[off] = hfn;
    }

    // hf_last appended after h_t
    out[(size_t)MDIM * MEM + (size_t)b * MEM + m] = hf;
}

// ---------------------------------------------------------------------------
// Launch
// inputs: d_in[0]=u [128,512,512] f32, d_in[1]=h0 [2,128,1024] f32,
//         d_in[2]=W_im [2048,512] f32, d_in[3]=b_im [2048] f32
// output: h_t [128,512,1024] f32 followed by hf_last [128,1024] f32
// ---------------------------------------------------------------------------
extern "C" void kernel_launch(void* const* d_in, const int* in_sizes, int n_in,
                              void* d_out, int out_size)
{
    const float* u    = (const float*)d_in[0];
    const float* h0   = (const float*)d_in[1];
    const float* W_im = (const float*)d_in[2];
    const float* b_im = (const float*)d_in[3];
    float* out = (float*)d_out;

    dim3 ggrid(NDIM / BN, MDIM / BM);  // (16, 512)
    gemm_epilogue_kernel<<<ggrid, 256>>>(u, W_im, b_im, out);

    scan_kernel<<<(BB * MEM) / 256, 256>>>(h0, out);
}

// round 8
// speedup vs baseline: 2.5406x; 2.5347x over previous
#include <cuda_runtime.h>
#include <cuda_bf16.h>
#include <math.h>
#include <stdint.h>

// ---------------------------------------------------------------------------
// Problem constants
// ---------------------------------------------------------------------------
#define BB   128
#define LL   512
#define MEM  1024
#define MDIM (BB * LL)     // 65536
#define NDIM (2 * MEM)     // 2048
#define KDIM 512

#define SOMA_FAST 4.0f
#define SOMA_SLOW 7.0f
#define MOD_BIAS  0.4f
#define EPS_BASE  0.9f
#define BIAS_MOD_RANGE 5.0f

// ---------------------------------------------------------------------------
// Device scratch (no allocations allowed)
// ---------------------------------------------------------------------------
__device__ float g_sb[(size_t)BB * LL * MEM];                         // 256 MiB
__device__ __align__(256) __nv_bfloat16 g_a[(size_t)2 * MDIM * KDIM]; // hi, lo
__device__ __align__(256) __nv_bfloat16 g_w[(size_t)2 * NDIM * KDIM]; // hi, lo

#define AOFF ((size_t)MDIM * KDIM)
#define WOFF ((size_t)NDIM * KDIM)

// ---------------------------------------------------------------------------
// PTX helpers (sm_80-era only: cp.async + ldmatrix + mma.sync — all legal on
// base sm_103 PTX target; tcgen05 is NOT, the harness emits .target sm_103)
// ---------------------------------------------------------------------------
__device__ __forceinline__ uint32_t smem_u32(const void* p) {
    uint32_t a;
    asm("{ .reg .u64 t; cvta.to.shared.u64 t, %1; cvt.u32.u64 %0, t; }"
        : "=r"(a) : "l"(p));
    return a;
}
__device__ __forceinline__ void cp16(uint32_t dst, const void* src) {
    asm volatile("cp.async.cg.shared.global [%0], [%1], 16;"
                 :: "r"(dst), "l"(__cvta_generic_to_global(src)) : "memory");
}
__device__ __forceinline__ void cp_commit() {
    asm volatile("cp.async.commit_group;" ::: "memory");
}
__device__ __forceinline__ void cp_wait1() {
    asm volatile("cp.async.wait_group 1;" ::: "memory");
}
__device__ __forceinline__ void ldsm_x4(uint32_t (&r)[4], uint32_t addr) {
    asm volatile("ldmatrix.sync.aligned.m8n8.x4.shared.b16 {%0,%1,%2,%3}, [%4];"
                 : "=r"(r[0]), "=r"(r[1]), "=r"(r[2]), "=r"(r[3]) : "r"(addr));
}
__device__ __forceinline__ void mma_bf16(float (&d)[4], const uint32_t (&a)[4],
                                         uint32_t b0, uint32_t b1) {
    asm volatile(
        "mma.sync.aligned.m16n8k16.row.col.f32.bf16.bf16.f32 "
        "{%0,%1,%2,%3}, {%4,%5,%6,%7}, {%8,%9}, {%0,%1,%2,%3};"
        : "+f"(d[0]), "+f"(d[1]), "+f"(d[2]), "+f"(d[3])
        : "r"(a[0]), "r"(a[1]), "r"(a[2]), "r"(a[3]), "r"(b0), "r"(b1));
}

#define SWZ(x) ((x) ^ (((x) >> 3) & 0x70))

// ---------------------------------------------------------------------------
// Split kernels: fp32 -> bf16 hi/lo
// ---------------------------------------------------------------------------
__device__ __forceinline__ void split1(float x, __nv_bfloat16& h, __nv_bfloat16& l) {
    h = __float2bfloat16(x);
    l = __float2bfloat16(x - __bfloat162float(h));
}

__global__ __launch_bounds__(256)
void split_a_kernel(const float* __restrict__ u)
{
    size_t i = (size_t)blockIdx.x * 256 + threadIdx.x;  // float4 index
    float4 v = ((const float4*)u)[i];
    __nv_bfloat16 h0, h1, h2, h3, l0, l1, l2, l3;
    split1(v.x, h0, l0); split1(v.y, h1, l1);
    split1(v.z, h2, l2); split1(v.w, h3, l3);
    __nv_bfloat162* ph = (__nv_bfloat162*)(g_a + 4 * i);
    __nv_bfloat162* pl = (__nv_bfloat162*)(g_a + AOFF + 4 * i);
    __nv_bfloat162 t;
    t.x = h0; t.y = h1; ph[0] = t;
    t.x = h2; t.y = h3; ph[1] = t;
    t.x = l0; t.y = l1; pl[0] = t;
    t.x = l2; t.y = l3; pl[1] = t;
}

__global__ __launch_bounds__(256)
void split_w_kernel(const float* __restrict__ W)
{
    size_t i = (size_t)blockIdx.x * 256 + threadIdx.x;
    float4 v = ((const float4*)W)[i];
    __nv_bfloat16 h0, h1, h2, h3, l0, l1, l2, l3;
    split1(v.x, h0, l0); split1(v.y, h1, l1);
    split1(v.z, h2, l2); split1(v.w, h3, l3);
    __nv_bfloat162* ph = (__nv_bfloat162*)(g_w + 4 * i);
    __nv_bfloat162* pl = (__nv_bfloat162*)(g_w + WOFF + 4 * i);
    __nv_bfloat162 t;
    t.x = h0; t.y = h1; ph[0] = t;
    t.x = h2; t.y = h3; ph[1] = t;
    t.x = l0; t.y = l1; pl[0] = t;
    t.x = l2; t.y = l3; pl[1] = t;
}

// ---------------------------------------------------------------------------
// HMMA GEMM: C[m,n] = sum_{3 passes} Ax[m,k] * Wx[n,k]  (bf16x3 split)
// CTA 128x128, 8 warps (4 M x 2 N), warp tile 32x64, mma.m16n8k16.
// BK = 64 bf16 (128 B rows, SW128 swizzle), 3-stage cp.async pipeline.
// Epilogue: n < MEM -> g_sb = 5*tanh(c/5);  n >= MEM -> out (io, in-place).
// ---------------------------------------------------------------------------
#define GBM 128
#define GBN 128
#define BKH 64
#define STAGES 3
#define NCHUNK 24                   // 3 passes * (512/64)
#define TILE_B (GBM * 128)          // 16 KB per tile per stage
#define GEMM_SMEM (2 * STAGES * TILE_B)  // 96 KB

__global__ __launch_bounds__(256, 2)
void gemm_hmma_kernel(const float* __restrict__ bias, float* __restrict__ out)
{
    extern __shared__ char smem[];
    const uint32_t sbase = smem_u32(smem);
    const int tid  = threadIdx.x;
    const int wid  = tid >> 5;
    const int lane = tid & 31;
    const int m0 = blockIdx.y * GBM;
    const int n0 = blockIdx.x * GBN;
    const int wm = wid & 3;        // 0..3 : M
    const int wn = wid >> 2;       // 0..1 : N

    // loader mapping: 256 threads, row = tid/8 (+32*it), 16B chunk = tid%8
    const int lrow = tid >> 3;
    const int lch  = tid & 7;

    float acc[2][8][4];
#pragma unroll
    for (int i = 0; i < 2; i++)
#pragma unroll
        for (int j = 0; j < 8; j++)
#pragma unroll
            for (int k = 0; k < 4; k++)
                acc[i][j][k] = 0.0f;

    // ---- async stage issue ----
    auto issue = [&](int c) {
        const int p  = c >> 3;                 // pass: 0 hi*hi, 1 lo*hi, 2 hi*lo
        const int kk = (c & 7) * BKH;
        const __nv_bfloat16* ab = g_a + ((p == 1) ? AOFF : 0)
                                      + (size_t)m0 * KDIM + kk;
        const __nv_bfloat16* wb = g_w + ((p == 2) ? WOFF : 0)
                                      + (size_t)n0 * KDIM + kk;
        const int st = c % STAGES;
        const uint32_t as_ = sbase + st * TILE_B;
        const uint32_t bs_ = sbase + (STAGES + st) * TILE_B;
#pragma unroll
        for (int it = 0; it < 4; it++) {
            const int r = lrow + it * 32;
            cp16(as_ + SWZ(r * 128 + lch * 16), ab + (size_t)r * KDIM + lch * 8);
            cp16(bs_ + SWZ(r * 128 + lch * 16), wb + (size_t)r * KDIM + lch * 8);
        }
        cp_commit();
    };

    issue(0);
    issue(1);

    for (int c = 0; c < NCHUNK; c++) {
        cp_wait1();
        __syncthreads();
        if (c + 2 < NCHUNK) issue(c + 2);
        else                cp_commit();   // keep wait_group accounting aligned

        const int st = c % STAGES;
        const uint32_t as_ = sbase + st * TILE_B;
        const uint32_t bs_ = sbase + (STAGES + st) * TILE_B;

#pragma unroll
        for (int ks = 0; ks < 4; ks++) {
            const int ch = ks * 2 + (lane >> 4);    // 16B chunk pair for this k16
            const int rsel = lane & 15;
            uint32_t a[2][4];
#pragma unroll
            for (int mt = 0; mt < 2; mt++) {
                const int r = wm * 32 + mt * 16 + rsel;
                ldsm_x4(a[mt], as_ + SWZ(r * 128 + ch * 16));
            }
            uint32_t b[4][4];
#pragma unroll
            for (int nt = 0; nt < 4; nt++) {
                const int r = wn * 64 + nt * 16 + rsel;
                ldsm_x4(b[nt], bs_ + SWZ(r * 128 + ch * 16));
            }
#pragma unroll
            for (int mt = 0; mt < 2; mt++)
#pragma unroll
                for (int nt = 0; nt < 4; nt++) {
                    mma_bf16(acc[mt][nt * 2 + 0], a[mt], b[nt][0], b[nt][2]);
                    mma_bf16(acc[mt][nt * 2 + 1], a[mt], b[nt][1], b[nt][3]);
                }
        }
    }

    // ---- epilogue ----
    const int gid = lane >> 2;
    const int tig = lane & 3;
    const bool is_sb = (n0 < MEM);
    const int ncol0 = n0 + wn * 64;

#pragma unroll
    for (int mt = 0; mt < 2; mt++) {
#pragma unroll
        for (int rh = 0; rh < 2; rh++) {       // c0,c1 at row gid; c2,c3 at gid+8
            const int row = m0 + wm * 32 + mt * 16 + gid + rh * 8;
            float* dst = is_sb ? (g_sb + (size_t)row * MEM + (ncol0))
                               : (out  + (size_t)row * MEM + (ncol0 - MEM));
#pragma unroll
            for (int nt8 = 0; nt8 < 8; nt8++) {
                const int col = nt8 * 8 + tig * 2;
                float2 v;
                v.x = acc[mt][nt8][rh * 2 + 0] + __ldg(&bias[ncol0 + col + 0]);
                v.y = acc[mt][nt8][rh * 2 + 1] + __ldg(&bias[ncol0 + col + 1]);
                if (is_sb) {
                    v.x = BIAS_MOD_RANGE * tanhf(v.x * (1.0f / BIAS_MOD_RANGE));
                    v.y = BIAS_MOD_RANGE * tanhf(v.y * (1.0f / BIAS_MOD_RANGE));
                }
                *(float2*)(dst + col) = v;
            }
        }
    }
}

// ---------------------------------------------------------------------------
// Scan: one thread per (b, m) state lane; 512 sequential timesteps.
// ---------------------------------------------------------------------------
__global__ __launch_bounds__(256)
void scan_kernel(const float* __restrict__ h0, float* __restrict__ out)
{
    const int idx = blockIdx.x * blockDim.x + threadIdx.x;
    const int b = idx >> 10;
    const int m = idx & (MEM - 1);

    float hf = h0[(size_t)b * MEM + m];
    float hs = h0[(size_t)BB * MEM + (size_t)b * MEM + m];

    const size_t base = (size_t)b * LL * MEM + m;
    const float* __restrict__ sbp = g_sb + base;
    float* __restrict__ op = out + base;

#pragma unroll 4
    for (int t = 0; t < LL; t++) {
        const size_t off = (size_t)t * MEM;
        float s  = sbp[off];
        float io = op[off];

        float d   = hs + MOD_BIAS;
        float arg = io + SOMA_FAST * hf - SOMA_SLOW * d * d + s;
        float hfn = tanhf(arg);

        float sg  = 1.0f / (1.0f + expf(-10.0f * (hf - 0.5f)));
        float eps = EPS_BASE + EPS_BASE * sg;
        hs = (1.0f - eps) * hs + eps * hf;
        hf = hfn;

        op[off] = hfn;
    }
    out[(size_t)MDIM * MEM + (size_t)b * MEM + m] = hf;
}

// ---------------------------------------------------------------------------
// Launch
// ---------------------------------------------------------------------------
extern "C" void kernel_launch(void* const* d_in, const int* in_sizes, int n_in,
                              void* d_out, int out_size)
{
    const float* u    = (const float*)d_in[0];
    const float* h0   = (const float*)d_in[1];
    const float* W_im = (const float*)d_in[2];
    const float* b_im = (const float*)d_in[3];
    float* out = (float*)d_out;

    cudaFuncSetAttribute(gemm_hmma_kernel,
                         cudaFuncAttributeMaxDynamicSharedMemorySize, GEMM_SMEM);

    split_a_kernel<<<(MDIM * KDIM / 4) / 256, 256>>>(u);
    split_w_kernel<<<(NDIM * KDIM / 4) / 256, 256>>>(W_im);

    dim3 ggrid(NDIM / GBN, MDIM / GBM);  // (16, 512)
    gemm_hmma_kernel<<<ggrid, 256, GEMM_SMEM>>>(b_im, out);

    scan_kernel<<<(BB * MEM) / 256, 256>>>(h0, out);
}

// round 11
// speedup vs baseline: 2.6594x; 1.0468x over previous
#include <cuda_runtime.h>
#include <cuda_bf16.h>
#include <math.h>
#include <stdint.h>

// ---------------------------------------------------------------------------
// Problem constants
// ---------------------------------------------------------------------------
#define BB   128
#define LL   512
#define MEM  1024
#define MDIM (BB * LL)     // 65536
#define NDIM (2 * MEM)     // 2048
#define KDIM 512

#define SOMA_FAST 4.0f
#define SOMA_SLOW 7.0f
#define MOD_BIAS  0.4f
#define EPS_BASE  0.9f
#define BIAS_MOD_RANGE 5.0f

// ---------------------------------------------------------------------------
// Device scratch (no allocations allowed)
// ---------------------------------------------------------------------------
__device__ float g_sb[(size_t)BB * LL * MEM];                         // 256 MiB
__device__ __align__(256) __nv_bfloat16 g_a[(size_t)2 * MDIM * KDIM]; // hi, lo
__device__ __align__(256) __nv_bfloat16 g_w[(size_t)2 * NDIM * KDIM]; // hi, lo

#define AOFF ((size_t)MDIM * KDIM)
#define WOFF ((size_t)NDIM * KDIM)

// ---------------------------------------------------------------------------
// PTX helpers (sm_80-era only; tcgen05 is rejected by this toolchain's
// .target sm_103 PTX)
// ---------------------------------------------------------------------------
__device__ __forceinline__ uint32_t smem_u32(const void* p) {
    uint32_t a;
    asm("{ .reg .u64 t; cvta.to.shared.u64 t, %1; cvt.u32.u64 %0, t; }"
        : "=r"(a) : "l"(p));
    return a;
}
__device__ __forceinline__ void cp16(uint32_t dst, const void* src) {
    asm volatile("cp.async.cg.shared.global [%0], [%1], 16;"
                 :: "r"(dst), "l"(__cvta_generic_to_global(src)) : "memory");
}
__device__ __forceinline__ void cp_commit() {
    asm volatile("cp.async.commit_group;" ::: "memory");
}
__device__ __forceinline__ void cp_wait1() {
    asm volatile("cp.async.wait_group 1;" ::: "memory");
}
__device__ __forceinline__ void ldsm_x4(uint32_t (&r)[4], uint32_t addr) {
    asm volatile("ldmatrix.sync.aligned.m8n8.x4.shared.b16 {%0,%1,%2,%3}, [%4];"
                 : "=r"(r[0]), "=r"(r[1]), "=r"(r[2]), "=r"(r[3]) : "r"(addr));
}
__device__ __forceinline__ void mma_bf16(float (&d)[4], const uint32_t (&a)[4],
                                         uint32_t b0, uint32_t b1) {
    asm volatile(
        "mma.sync.aligned.m16n8k16.row.col.f32.bf16.bf16.f32 "
        "{%0,%1,%2,%3}, {%4,%5,%6,%7}, {%8,%9}, {%0,%1,%2,%3};"
        : "+f"(d[0]), "+f"(d[1]), "+f"(d[2]), "+f"(d[3])
        : "r"(a[0]), "r"(a[1]), "r"(a[2]), "r"(a[3]), "r"(b0), "r"(b1));
}

#define SWZ(x) ((x) ^ (((x) >> 3) & 0x70))

// ---------------------------------------------------------------------------
// Split kernels: fp32 -> bf16 hi/lo
// ---------------------------------------------------------------------------
__device__ __forceinline__ void split1(float x, __nv_bfloat16& h, __nv_bfloat16& l) {
    h = __float2bfloat16(x);
    l = __float2bfloat16(x - __bfloat162float(h));
}

__global__ __launch_bounds__(256)
void split_a_kernel(const float* __restrict__ u)
{
    size_t i = (size_t)blockIdx.x * 256 + threadIdx.x;  // float4 index
    float4 v = ((const float4*)u)[i];
    __nv_bfloat16 h0, h1, h2, h3, l0, l1, l2, l3;
    split1(v.x, h0, l0); split1(v.y, h1, l1);
    split1(v.z, h2, l2); split1(v.w, h3, l3);
    __nv_bfloat162* ph = (__nv_bfloat162*)(g_a + 4 * i);
    __nv_bfloat162* pl = (__nv_bfloat162*)(g_a + AOFF + 4 * i);
    __nv_bfloat162 t;
    t.x = h0; t.y = h1; ph[0] = t;
    t.x = h2; t.y = h3; ph[1] = t;
    t.x = l0; t.y = l1; pl[0] = t;
    t.x = l2; t.y = l3; pl[1] = t;
}

__global__ __launch_bounds__(256)
void split_w_kernel(const float* __restrict__ W)
{
    size_t i = (size_t)blockIdx.x * 256 + threadIdx.x;
    float4 v = ((const float4*)W)[i];
    __nv_bfloat16 h0, h1, h2, h3, l0, l1, l2, l3;
    split1(v.x, h0, l0); split1(v.y, h1, l1);
    split1(v.z, h2, l2); split1(v.w, h3, l3);
    __nv_bfloat162* ph = (__nv_bfloat162*)(g_w + 4 * i);
    __nv_bfloat162* pl = (__nv_bfloat162*)(g_w + WOFF + 4 * i);
    __nv_bfloat162 t;
    t.x = h0; t.y = h1; ph[0] = t;
    t.x = h2; t.y = h3; ph[1] = t;
    t.x = l0; t.y = l1; pl[0] = t;
    t.x = l2; t.y = l3; pl[1] = t;
}

// ---------------------------------------------------------------------------
// HMMA GEMM: C[m,n] = sum_{3 passes} Ax[m,k] * Wx[n,k]  (bf16x3 split)
// CTA 256x128, 16 warps (8 M x 2 N), warp tile 32x64, mma.m16n8k16.
// BK = 64 bf16 (128 B rows, SW128 swizzle), 3-stage cp.async pipeline.
// Epilogue: n < MEM -> g_sb = 5*tanh(c/5);  n >= MEM -> out (io, in-place).
// ---------------------------------------------------------------------------
#define GBM 256
#define GBN 128
#define BKH 64
#define STAGES 3
#define NCHUNK 24                   // 3 passes * (512/64)
#define A_TILE_B (GBM * 128)        // 32 KB per stage
#define B_TILE_B (GBN * 128)        // 16 KB per stage
#define GEMM_SMEM (STAGES * (A_TILE_B + B_TILE_B))  // 144 KB

__global__ __launch_bounds__(512, 1)
void gemm_hmma_kernel(const float* __restrict__ bias, float* __restrict__ out)
{
    extern __shared__ char smem[];
    const uint32_t sbase = smem_u32(smem);
    const int tid  = threadIdx.x;
    const int wid  = tid >> 5;
    const int lane = tid & 31;
    const int m0 = blockIdx.y * GBM;
    const int n0 = blockIdx.x * GBN;
    const int wm = wid & 7;        // 0..7 : M (32-row strip)
    const int wn = wid >> 3;       // 0..1 : N (64-col strip)

    // loader mapping: 512 threads, row = tid/8 (+64*it), 16B chunk = tid%8
    const int lrow = tid >> 3;     // 0..63
    const int lch  = tid & 7;

    float acc[2][8][4];
#pragma unroll
    for (int i = 0; i < 2; i++)
#pragma unroll
        for (int j = 0; j < 8; j++)
#pragma unroll
            for (int k = 0; k < 4; k++)
                acc[i][j][k] = 0.0f;

    auto issue = [&](int c) {
        const int p  = c >> 3;                 // pass: 0 hi*hi, 1 lo*hi, 2 hi*lo
        const int kk = (c & 7) * BKH;
        const __nv_bfloat16* ab = g_a + ((p == 1) ? AOFF : 0)
                                      + (size_t)m0 * KDIM + kk;
        const __nv_bfloat16* wb = g_w + ((p == 2) ? WOFF : 0)
                                      + (size_t)n0 * KDIM + kk;
        const int st = c % STAGES;
        const uint32_t as_ = sbase + st * (A_TILE_B + B_TILE_B);
        const uint32_t bs_ = as_ + A_TILE_B;
#pragma unroll
        for (int it = 0; it < 4; it++) {       // A: 256 rows
            const int r = lrow + it * 64;
            cp16(as_ + SWZ(r * 128 + lch * 16), ab + (size_t)r * KDIM + lch * 8);
        }
#pragma unroll
        for (int it = 0; it < 2; it++) {       // B: 128 rows
            const int r = lrow + it * 64;
            cp16(bs_ + SWZ(r * 128 + lch * 16), wb + (size_t)r * KDIM + lch * 8);
        }
        cp_commit();
    };

    issue(0);
    issue(1);

    for (int c = 0; c < NCHUNK; c++) {
        cp_wait1();
        __syncthreads();
        if (c + 2 < NCHUNK) issue(c + 2);
        else                cp_commit();   // keep wait_group accounting aligned

        const int st = c % STAGES;
        const uint32_t as_ = sbase + st * (A_TILE_B + B_TILE_B);
        const uint32_t bs_ = as_ + A_TILE_B;

#pragma unroll
        for (int ks = 0; ks < 4; ks++) {
            const int ch = ks * 2 + (lane >> 4);    // 16B chunk pair for this k16
            const int rsel = lane & 15;
            uint32_t a[2][4];
#pragma unroll
            for (int mt = 0; mt < 2; mt++) {
                const int r = wm * 32 + mt * 16 + rsel;
                ldsm_x4(a[mt], as_ + SWZ(r * 128 + ch * 16));
            }
            uint32_t b[4][4];
#pragma unroll
            for (int nt = 0; nt < 4; nt++) {
                const int r = wn * 64 + nt * 16 + rsel;
                ldsm_x4(b[nt], bs_ + SWZ(r * 128 + ch * 16));
            }
#pragma unroll
            for (int mt = 0; mt < 2; mt++)
#pragma unroll
                for (int nt = 0; nt < 4; nt++) {
                    mma_bf16(acc[mt][nt * 2 + 0], a[mt], b[nt][0], b[nt][2]);
                    mma_bf16(acc[mt][nt * 2 + 1], a[mt], b[nt][1], b[nt][3]);
                }
        }
    }

    // ---- epilogue ----
    const int gid = lane >> 2;
    const int tig = lane & 3;
    const bool is_sb = (n0 < MEM);
    const int ncol0 = n0 + wn * 64;

#pragma unroll
    for (int mt = 0; mt < 2; mt++) {
#pragma unroll
        for (int rh = 0; rh < 2; rh++) {
            const int row = m0 + wm * 32 + mt * 16 + gid + rh * 8;
            float* dst = is_sb ? (g_sb + (size_t)row * MEM + ncol0)
                               : (out  + (size_t)row * MEM + (ncol0 - MEM));
#pragma unroll
            for (int nt8 = 0; nt8 < 8; nt8++) {
                const int col = nt8 * 8 + tig * 2;
                float2 v;
                v.x = acc[mt][nt8][rh * 2 + 0] + __ldg(&bias[ncol0 + col + 0]);
                v.y = acc[mt][nt8][rh * 2 + 1] + __ldg(&bias[ncol0 + col + 1]);
                if (is_sb) {
                    v.x = BIAS_MOD_RANGE * tanhf(v.x * (1.0f / BIAS_MOD_RANGE));
                    v.y = BIAS_MOD_RANGE * tanhf(v.y * (1.0f / BIAS_MOD_RANGE));
                }
                *(float2*)(dst + col) = v;
            }
        }
    }
}

// ---------------------------------------------------------------------------
// Scan: one thread per (b, m) lane; 512 sequential steps.
// Software-pipelined: prefetch depth PD=8 (rolling register arrays) so ~16
// loads are in flight per thread; streaming ld/st hints (data has no reuse).
// ---------------------------------------------------------------------------
#define PD 8

__global__ __launch_bounds__(256)
void scan_kernel(const float* __restrict__ h0, float* __restrict__ out)
{
    const int idx = blockIdx.x * blockDim.x + threadIdx.x;
    const int b = idx >> 10;
    const int m = idx & (MEM - 1);

    float hf = h0[(size_t)b * MEM + m];
    float hs = h0[(size_t)BB * MEM + (size_t)b * MEM + m];

    const size_t base = (size_t)b * LL * MEM + m;
    const float* __restrict__ sbp = g_sb + base;
    float* __restrict__ op = out + base;

    float sbv[PD], iov[PD];
#pragma unroll
    for (int j = 0; j < PD; j++) {
        sbv[j] = __ldcs(sbp + (size_t)j * MEM);
        iov[j] = __ldcs(op  + (size_t)j * MEM);
    }

#pragma unroll 1
    for (int t = 0; t < LL; t += PD) {
#pragma unroll
        for (int j = 0; j < PD; j++) {
            const float s  = sbv[j];
            const float io = iov[j];

            // prefetch PD ahead (last block: guarded out)
            if (t + PD + j < LL) {
                sbv[j] = __ldcs(sbp + (size_t)(t + PD + j) * MEM);
                iov[j] = __ldcs(op  + (size_t)(t + PD + j) * MEM);
            }

            const float d   = hs + MOD_BIAS;
            const float arg = io + SOMA_FAST * hf - SOMA_SLOW * d * d + s;
            const float hfn = tanhf(arg);

            const float sg  = 1.0f / (1.0f + expf(-10.0f * (hf - 0.5f)));
            const float eps = EPS_BASE + EPS_BASE * sg;
            hs = (1.0f - eps) * hs + eps * hf;
            hf = hfn;

            __stcs(op + (size_t)(t + j) * MEM, hfn);
        }
    }
    out[(size_t)MDIM * MEM + (size_t)b * MEM + m] = hf;
}

// ---------------------------------------------------------------------------
// Launch
// ---------------------------------------------------------------------------
extern "C" void kernel_launch(void* const* d_in, const int* in_sizes, int n_in,
                              void* d_out, int out_size)
{
    const float* u    = (const float*)d_in[0];
    const float* h0   = (const float*)d_in[1];
    const float* W_im = (const float*)d_in[2];
    const float* b_im = (const float*)d_in[3];
    float* out = (float*)d_out;

    cudaFuncSetAttribute(gemm_hmma_kernel,
                         cudaFuncAttributeMaxDynamicSharedMemorySize, GEMM_SMEM);

    split_w_kernel<<<(NDIM * KDIM / 4) / 256, 256>>>(W_im);
    split_a_kernel<<<(MDIM * KDIM / 4) / 256, 256>>>(u);

    dim3 ggrid(NDIM / GBN, MDIM / GBM);  // (16, 256)
    gemm_hmma_kernel<<<ggrid, 512, GEMM_SMEM>>>(b_im, out);

    scan_kernel<<<(BB * MEM) / 256, 256>>>(h0, out);
}

// round 12
// speedup vs baseline: 2.8693x; 1.0790x over previous
#include <cuda_runtime.h>
#include <cuda_bf16.h>
#include <math.h>
#include <stdint.h>

// ---------------------------------------------------------------------------
// Problem constants
// ---------------------------------------------------------------------------
#define BB   128
#define LL   512
#define MEM  1024
#define MDIM (BB * LL)     // 65536
#define NDIM (2 * MEM)     // 2048
#define KDIM 512

#define SOMA_FAST 4.0f
#define SOMA_SLOW 7.0f
#define MOD_BIAS  0.4f
#define EPS_BASE  0.9f
#define BIAS_MOD_RANGE 5.0f

// ---------------------------------------------------------------------------
// Device scratch (no allocations allowed)
// ---------------------------------------------------------------------------
__device__ float g_sb[(size_t)BB * LL * MEM];                         // 256 MiB
__device__ __align__(256) __nv_bfloat16 g_a[(size_t)2 * MDIM * KDIM]; // hi, lo
__device__ __align__(256) __nv_bfloat16 g_w[(size_t)2 * NDIM * KDIM]; // hi, lo

#define AOFF ((size_t)MDIM * KDIM)
#define WOFF ((size_t)NDIM * KDIM)

// ---------------------------------------------------------------------------
// PTX helpers (sm_80-era only; tcgen05 is rejected by this toolchain's
// .target sm_103 PTX)
// ---------------------------------------------------------------------------
__device__ __forceinline__ uint32_t smem_u32(const void* p) {
    uint32_t a;
    asm("{ .reg .u64 t; cvta.to.shared.u64 t, %1; cvt.u32.u64 %0, t; }"
        : "=r"(a) : "l"(p));
    return a;
}
__device__ __forceinline__ void cp16(uint32_t dst, const void* src) {
    asm volatile("cp.async.cg.shared.global [%0], [%1], 16;"
                 :: "r"(dst), "l"(__cvta_generic_to_global(src)) : "memory");
}
__device__ __forceinline__ void cp_commit() {
    asm volatile("cp.async.commit_group;" ::: "memory");
}
__device__ __forceinline__ void cp_wait1() {
    asm volatile("cp.async.wait_group 1;" ::: "memory");
}
__device__ __forceinline__ void ldsm_x4(uint32_t (&r)[4], uint32_t addr) {
    asm volatile("ldmatrix.sync.aligned.m8n8.x4.shared.b16 {%0,%1,%2,%3}, [%4];"
                 : "=r"(r[0]), "=r"(r[1]), "=r"(r[2]), "=r"(r[3]) : "r"(addr));
}
__device__ __forceinline__ void mma_bf16(float (&d)[4], const uint32_t (&a)[4],
                                         uint32_t b0, uint32_t b1) {
    asm volatile(
        "mma.sync.aligned.m16n8k16.row.col.f32.bf16.bf16.f32 "
        "{%0,%1,%2,%3}, {%4,%5,%6,%7}, {%8,%9}, {%0,%1,%2,%3};"
        : "+f"(d[0]), "+f"(d[1]), "+f"(d[2]), "+f"(d[3])
        : "r"(a[0]), "r"(a[1]), "r"(a[2]), "r"(a[3]), "r"(b0), "r"(b1));
}

#define SWZ(x) ((x) ^ (((x) >> 3) & 0x70))

// ---------------------------------------------------------------------------
// Split kernels: fp32 -> bf16 hi/lo
// ---------------------------------------------------------------------------
__device__ __forceinline__ void split1(float x, __nv_bfloat16& h, __nv_bfloat16& l) {
    h = __float2bfloat16(x);
    l = __float2bfloat16(x - __bfloat162float(h));
}

__global__ __launch_bounds__(256)
void split_a_kernel(const float* __restrict__ u)
{
    size_t i = (size_t)blockIdx.x * 256 + threadIdx.x;  // float4 index
    float4 v = ((const float4*)u)[i];
    __nv_bfloat16 h0, h1, h2, h3, l0, l1, l2, l3;
    split1(v.x, h0, l0); split1(v.y, h1, l1);
    split1(v.z, h2, l2); split1(v.w, h3, l3);
    __nv_bfloat162* ph = (__nv_bfloat162*)(g_a + 4 * i);
    __nv_bfloat162* pl = (__nv_bfloat162*)(g_a + AOFF + 4 * i);
    __nv_bfloat162 t;
    t.x = h0; t.y = h1; ph[0] = t;
    t.x = h2; t.y = h3; ph[1] = t;
    t.x = l0; t.y = l1; pl[0] = t;
    t.x = l2; t.y = l3; pl[1] = t;
}

__global__ __launch_bounds__(256)
void split_w_kernel(const float* __restrict__ W)
{
    size_t i = (size_t)blockIdx.x * 256 + threadIdx.x;
    float4 v = ((const float4*)W)[i];
    __nv_bfloat16 h0, h1, h2, h3, l0, l1, l2, l3;
    split1(v.x, h0, l0); split1(v.y, h1, l1);
    split1(v.z, h2, l2); split1(v.w, h3, l3);
    __nv_bfloat162* ph = (__nv_bfloat162*)(g_w + 4 * i);
    __nv_bfloat162* pl = (__nv_bfloat162*)(g_w + WOFF + 4 * i);
    __nv_bfloat162 t;
    t.x = h0; t.y = h1; ph[0] = t;
    t.x = h2; t.y = h3; ph[1] = t;
    t.x = l0; t.y = l1; pl[0] = t;
    t.x = l2; t.y = l3; pl[1] = t;
}

// ---------------------------------------------------------------------------
// HMMA GEMM: C[m,n] = sum_{3 passes} Ax[m,k] * Wx[n,k]  (bf16x3 split)
// CTA 128x128, 4 warps (2 M x 2 N), warp tile 64x64, mma.m16n8k16.
// BK = 64 bf16 (128 B rows, SW128 swizzle), 3-stage cp.async pipeline,
// 2 CTAs/SM. Epilogue: n < MEM -> g_sb = 5*tanh(c/5); n >= MEM -> out (io).
// ---------------------------------------------------------------------------
#define GBM 128
#define GBN 128
#define BKH 64
#define STAGES 3
#define NCHUNK 24                   // 3 passes * (512/64)
#define TILE_B (GBM * 128)          // 16 KB per tile per stage
#define GEMM_SMEM (2 * STAGES * TILE_B)  // 96 KB

__global__ __launch_bounds__(128, 2)
void gemm_hmma_kernel(const float* __restrict__ bias, float* __restrict__ out)
{
    extern __shared__ char smem[];
    const uint32_t sbase = smem_u32(smem);
    const int tid  = threadIdx.x;
    const int wid  = tid >> 5;
    const int lane = tid & 31;
    const int m0 = blockIdx.y * GBM;
    const int n0 = blockIdx.x * GBN;
    const int wm = wid & 1;        // 0..1 : M (64-row strip)
    const int wn = wid >> 1;       // 0..1 : N (64-col strip)

    // loader mapping: 128 threads, row = tid/8 (+16*it), 16B chunk = tid%8
    const int lrow = tid >> 3;     // 0..15
    const int lch  = tid & 7;

    float acc[4][8][4];            // [mt][n8][frag] = 128 regs
#pragma unroll
    for (int i = 0; i < 4; i++)
#pragma unroll
        for (int j = 0; j < 8; j++)
#pragma unroll
            for (int k = 0; k < 4; k++)
                acc[i][j][k] = 0.0f;

    auto issue = [&](int c) {
        const int p  = c >> 3;                 // pass: 0 hi*hi, 1 lo*hi, 2 hi*lo
        const int kk = (c & 7) * BKH;
        const __nv_bfloat16* ab = g_a + ((p == 1) ? AOFF : 0)
                                      + (size_t)m0 * KDIM + kk;
        const __nv_bfloat16* wb = g_w + ((p == 2) ? WOFF : 0)
                                      + (size_t)n0 * KDIM + kk;
        const int st = c % STAGES;
        const uint32_t as_ = sbase + st * TILE_B;
        const uint32_t bs_ = sbase + (STAGES + st) * TILE_B;
#pragma unroll
        for (int it = 0; it < 8; it++) {       // 128 rows each
            const int r = lrow + it * 16;
            cp16(as_ + SWZ(r * 128 + lch * 16), ab + (size_t)r * KDIM + lch * 8);
            cp16(bs_ + SWZ(r * 128 + lch * 16), wb + (size_t)r * KDIM + lch * 8);
        }
        cp_commit();
    };

    issue(0);
    issue(1);

    const int rsel  = lane & 15;
    const int chsel = lane >> 4;   // 0/1

    for (int c = 0; c < NCHUNK; c++) {
        cp_wait1();
        __syncthreads();
        if (c + 2 < NCHUNK) issue(c + 2);
        else                cp_commit();   // keep wait_group accounting aligned

        const int st = c % STAGES;
        const uint32_t as_ = sbase + st * TILE_B;
        const uint32_t bs_ = sbase + (STAGES + st) * TILE_B;

#pragma unroll
        for (int ks = 0; ks < 4; ks++) {
            const int ch = ks * 2 + chsel;      // 16B chunk pair for this k16
            uint32_t a[4][4];
#pragma unroll
            for (int mt = 0; mt < 4; mt++) {
                const int r = wm * 64 + mt * 16 + rsel;
                ldsm_x4(a[mt], as_ + SWZ(r * 128 + ch * 16));
            }
            uint32_t b[4][4];
#pragma unroll
            for (int nt = 0; nt < 4; nt++) {
                const int r = wn * 64 + nt * 16 + rsel;
                ldsm_x4(b[nt], bs_ + SWZ(r * 128 + ch * 16));
            }
#pragma unroll
            for (int mt = 0; mt < 4; mt++)
#pragma unroll
                for (int nt = 0; nt < 4; nt++) {
                    mma_bf16(acc[mt][nt * 2 + 0], a[mt], b[nt][0], b[nt][2]);
                    mma_bf16(acc[mt][nt * 2 + 1], a[mt], b[nt][1], b[nt][3]);
                }
        }
    }

    // ---- epilogue ----
    const int gid = lane >> 2;
    const int tig = lane & 3;
    const bool is_sb = (n0 < MEM);
    const int ncol0 = n0 + wn * 64;

#pragma unroll
    for (int mt = 0; mt < 4; mt++) {
#pragma unroll
        for (int rh = 0; rh < 2; rh++) {
            const int row = m0 + wm * 64 + mt * 16 + gid + rh * 8;
            float* dst = is_sb ? (g_sb + (size_t)row * MEM + ncol0)
                               : (out  + (size_t)row * MEM + (ncol0 - MEM));
#pragma unroll
            for (int nt8 = 0; nt8 < 8; nt8++) {
                const int col = nt8 * 8 + tig * 2;
                float2 v;
                v.x = acc[mt][nt8][rh * 2 + 0] + __ldg(&bias[ncol0 + col + 0]);
                v.y = acc[mt][nt8][rh * 2 + 1] + __ldg(&bias[ncol0 + col + 1]);
                if (is_sb) {
                    v.x = BIAS_MOD_RANGE * tanhf(v.x * (1.0f / BIAS_MOD_RANGE));
                    v.y = BIAS_MOD_RANGE * tanhf(v.y * (1.0f / BIAS_MOD_RANGE));
                }
                *(float2*)(dst + col) = v;
            }
        }
    }
}

// ---------------------------------------------------------------------------
// Scan: one thread per (b, m) lane; 512 sequential steps.
// Software-pipelined prefetch depth PD=16 (rolling register arrays) -> ~32
// loads in flight per thread; streaming ld/st hints (no reuse).
// ---------------------------------------------------------------------------
#define PD 16

__global__ __launch_bounds__(256)
void scan_kernel(const float* __restrict__ h0, float* __restrict__ out)
{
    const int idx = blockIdx.x * blockDim.x + threadIdx.x;
    const int b = idx >> 10;
    const int m = idx & (MEM - 1);

    float hf = h0[(size_t)b * MEM + m];
    float hs = h0[(size_t)BB * MEM + (size_t)b * MEM + m];

    const size_t base = (size_t)b * LL * MEM + m;
    const float* __restrict__ sbp = g_sb + base;
    float* __restrict__ op = out + base;

    float sbv[PD], iov[PD];
#pragma unroll
    for (int j = 0; j < PD; j++) {
        sbv[j] = __ldcs(sbp + (size_t)j * MEM);
        iov[j] = __ldcs(op  + (size_t)j * MEM);
    }

#pragma unroll 1
    for (int t = 0; t < LL; t += PD) {
#pragma unroll
        for (int j = 0; j < PD; j++) {
            const float s  = sbv[j];
            const float io = iov[j];

            if (t + PD + j < LL) {
                sbv[j] = __ldcs(sbp + (size_t)(t + PD + j) * MEM);
                iov[j] = __ldcs(op  + (size_t)(t + PD + j) * MEM);
            }

            const float d   = hs + MOD_BIAS;
            const float arg = io + SOMA_FAST * hf - SOMA_SLOW * d * d + s;
            const float hfn = tanhf(arg);

            const float sg  = 1.0f / (1.0f + expf(-10.0f * (hf - 0.5f)));
            const float eps = EPS_BASE + EPS_BASE * sg;
            hs = (1.0f - eps) * hs + eps * hf;
            hf = hfn;

            __stcs(op + (size_t)(t + j) * MEM, hfn);
        }
    }
    out[(size_t)MDIM * MEM + (size_t)b * MEM + m] = hf;
}

// ---------------------------------------------------------------------------
// Launch
// ---------------------------------------------------------------------------
extern "C" void kernel_launch(void* const* d_in, const int* in_sizes, int n_in,
                              void* d_out, int out_size)
{
    const float* u    = (const float*)d_in[0];
    const float* h0   = (const float*)d_in[1];
    const float* W_im = (const float*)d_in[2];
    const float* b_im = (const float*)d_in[3];
    float* out = (float*)d_out;

    cudaFuncSetAttribute(gemm_hmma_kernel,
                         cudaFuncAttributeMaxDynamicSharedMemorySize, GEMM_SMEM);

    split_w_kernel<<<(NDIM * KDIM / 4) / 256, 256>>>(W_im);
    split_a_kernel<<<(MDIM * KDIM / 4) / 256, 256>>>(u);

    dim3 ggrid(NDIM / GBN, MDIM / GBM);  // (16, 512)
    gemm_hmma_kernel<<<ggrid, 128, GEMM_SMEM>>>(b_im, out);

    scan_kernel<<<(BB * MEM) / 256, 256>>>(h0, out);
}

// round 13
// speedup vs baseline: 2.8811x; 1.0041x over previous
#include <cuda_runtime.h>
#include <cuda_bf16.h>
#include <math.h>
#include <stdint.h>

// ---------------------------------------------------------------------------
// Problem constants
// ---------------------------------------------------------------------------
#define BB   128
#define LL   512
#define MEM  1024
#define MDIM (BB * LL)     // 65536
#define NDIM (2 * MEM)     // 2048
#define KDIM 512

#define SOMA_FAST 4.0f
#define SOMA_SLOW 7.0f
#define MOD_BIAS  0.4f
#define EPS_BASE  0.9f
#define BIAS_MOD_RANGE 5.0f

// ---------------------------------------------------------------------------
// Device scratch (no allocations allowed)
// ---------------------------------------------------------------------------
__device__ float g_sb[(size_t)BB * LL * MEM];                         // 256 MiB
__device__ __align__(256) __nv_bfloat16 g_a[(size_t)2 * MDIM * KDIM]; // hi, lo
__device__ __align__(256) __nv_bfloat16 g_w[(size_t)2 * NDIM * KDIM]; // hi, lo

#define AOFF ((size_t)MDIM * KDIM)
#define WOFF ((size_t)NDIM * KDIM)

// ---------------------------------------------------------------------------
// PTX helpers (sm_80-era only; tcgen05 is rejected by this toolchain's
// .target sm_103 PTX)
// ---------------------------------------------------------------------------
__device__ __forceinline__ uint32_t smem_u32(const void* p) {
    uint32_t a;
    asm("{ .reg .u64 t; cvta.to.shared.u64 t, %1; cvt.u32.u64 %0, t; }"
        : "=r"(a) : "l"(p));
    return a;
}
__device__ __forceinline__ void cp16(uint32_t dst, const void* src) {
    asm volatile("cp.async.cg.shared.global [%0], [%1], 16;"
                 :: "r"(dst), "l"(__cvta_generic_to_global(src)) : "memory");
}
__device__ __forceinline__ void cp_commit() {
    asm volatile("cp.async.commit_group;" ::: "memory");
}
__device__ __forceinline__ void cp_wait1() {
    asm volatile("cp.async.wait_group 1;" ::: "memory");
}
__device__ __forceinline__ void ldsm_x4(uint32_t (&r)[4], uint32_t addr) {
    asm volatile("ldmatrix.sync.aligned.m8n8.x4.shared.b16 {%0,%1,%2,%3}, [%4];"
                 : "=r"(r[0]), "=r"(r[1]), "=r"(r[2]), "=r"(r[3]) : "r"(addr));
}
__device__ __forceinline__ void mma_bf16(float (&d)[4], const uint32_t (&a)[4],
                                         uint32_t b0, uint32_t b1) {
    asm volatile(
        "mma.sync.aligned.m16n8k16.row.col.f32.bf16.bf16.f32 "
        "{%0,%1,%2,%3}, {%4,%5,%6,%7}, {%8,%9}, {%0,%1,%2,%3};"
        : "+f"(d[0]), "+f"(d[1]), "+f"(d[2]), "+f"(d[3])
        : "r"(a[0]), "r"(a[1]), "r"(a[2]), "r"(a[3]), "r"(b0), "r"(b1));
}

#define SWZ(x) ((x) ^ (((x) >> 3) & 0x70))

// ---------------------------------------------------------------------------
// Split kernels: fp32 -> bf16 hi/lo
// ---------------------------------------------------------------------------
__device__ __forceinline__ void split1(float x, __nv_bfloat16& h, __nv_bfloat16& l) {
    h = __float2bfloat16(x);
    l = __float2bfloat16(x - __bfloat162float(h));
}

__global__ __launch_bounds__(256)
void split_a_kernel(const float* __restrict__ u)
{
    size_t i = (size_t)blockIdx.x * 256 + threadIdx.x;  // float4 index
    float4 v = ((const float4*)u)[i];
    __nv_bfloat16 h0, h1, h2, h3, l0, l1, l2, l3;
    split1(v.x, h0, l0); split1(v.y, h1, l1);
    split1(v.z, h2, l2); split1(v.w, h3, l3);
    __nv_bfloat162* ph = (__nv_bfloat162*)(g_a + 4 * i);
    __nv_bfloat162* pl = (__nv_bfloat162*)(g_a + AOFF + 4 * i);
    __nv_bfloat162 t;
    t.x = h0; t.y = h1; ph[0] = t;
    t.x = h2; t.y = h3; ph[1] = t;
    t.x = l0; t.y = l1; pl[0] = t;
    t.x = l2; t.y = l3; pl[1] = t;
}

__global__ __launch_bounds__(256)
void split_w_kernel(const float* __restrict__ W)
{
    size_t i = (size_t)blockIdx.x * 256 + threadIdx.x;
    float4 v = ((const float4*)W)[i];
    __nv_bfloat16 h0, h1, h2, h3, l0, l1, l2, l3;
    split1(v.x, h0, l0); split1(v.y, h1, l1);
    split1(v.z, h2, l2); split1(v.w, h3, l3);
    __nv_bfloat162* ph = (__nv_bfloat162*)(g_w + 4 * i);
    __nv_bfloat162* pl = (__nv_bfloat162*)(g_w + WOFF + 4 * i);
    __nv_bfloat162 t;
    t.x = h0; t.y = h1; ph[0] = t;
    t.x = h2; t.y = h3; ph[1] = t;
    t.x = l0; t.y = l1; pl[0] = t;
    t.x = l2; t.y = l3; pl[1] = t;
}

// ---------------------------------------------------------------------------
// HMMA GEMM: C[m,n] = sum_{3 passes} Ax[m,k] * Wx[n,k]  (bf16x3 split)
// CTA 128x128, 4 warps (2 M x 2 N), warp tile 64x64, mma.m16n8k16.
// BK = 64 bf16 (128 B rows, SW128 swizzle), 3-stage cp.async pipeline,
// 2 CTAs/SM.
// Chunk order per k-chunk: {A_hi*W_hi, A_hi*W_lo, A_lo*W_hi} so sub-chunks
// 0,1 share one A stage (A-event e=(2c)/3, A stage e%3, B stage c%3).
// Fragment double-buffering across the 4 ks-steps inside each chunk.
// Epilogue: n < MEM -> g_sb = 5*tanh(c/5); n >= MEM -> out (io, in-place).
// ---------------------------------------------------------------------------
#define GBM 128
#define GBN 128
#define BKH 64
#define STAGES 3
#define NCHUNK 24                   // 8 k-chunks * 3 sub-passes
#define TILE_B (GBM * 128)          // 16 KB per tile per stage
#define GEMM_SMEM (2 * STAGES * TILE_B)  // 96 KB

__global__ __launch_bounds__(128, 2)
void gemm_hmma_kernel(const float* __restrict__ bias, float* __restrict__ out)
{
    extern __shared__ char smem[];
    const uint32_t sbase = smem_u32(smem);
    const int tid  = threadIdx.x;
    const int wid  = tid >> 5;
    const int lane = tid & 31;
    const int m0 = blockIdx.y * GBM;
    const int n0 = blockIdx.x * GBN;
    const int wm = wid & 1;        // 0..1 : M (64-row strip)
    const int wn = wid >> 1;       // 0..1 : N (64-col strip)

    // loader mapping: 128 threads, row = tid/8 (+16*it), 16B chunk = tid%8
    const int lrow = tid >> 3;     // 0..15
    const int lch  = tid & 7;

    float acc[4][8][4];            // [mt][n8][frag] = 128 regs
#pragma unroll
    for (int i = 0; i < 4; i++)
#pragma unroll
        for (int j = 0; j < 8; j++)
#pragma unroll
            for (int k = 0; k < 4; k++)
                acc[i][j][k] = 0.0f;

    auto issue = [&](int c) {
        const int k8  = c / 3;
        const int sub = c - k8 * 3;            // 0: hi*hi  1: hi*lo  2: lo*hi
        const int kk  = k8 * BKH;
        const uint32_t as_ = sbase + (((2 * c) / 3) % STAGES) * TILE_B;
        const uint32_t bs_ = sbase + (STAGES + c % STAGES) * TILE_B;
        if (sub != 1) {                        // sub1 reuses sub0's A stage
            const __nv_bfloat16* ab = g_a + ((sub == 2) ? AOFF : 0)
                                          + (size_t)m0 * KDIM + kk;
#pragma unroll
            for (int it = 0; it < 8; it++) {
                const int r = lrow + it * 16;
                cp16(as_ + SWZ(r * 128 + lch * 16), ab + (size_t)r * KDIM + lch * 8);
            }
        }
        const __nv_bfloat16* wb = g_w + ((sub == 1) ? WOFF : 0)
                                      + (size_t)n0 * KDIM + kk;
#pragma unroll
        for (int it = 0; it < 8; it++) {
            const int r = lrow + it * 16;
            cp16(bs_ + SWZ(r * 128 + lch * 16), wb + (size_t)r * KDIM + lch * 8);
        }
        cp_commit();
    };

    issue(0);
    issue(1);

    const int rsel  = lane & 15;
    const int chsel = lane >> 4;   // 0/1

    for (int c = 0; c < NCHUNK; c++) {
        cp_wait1();
        __syncthreads();
        if (c + 2 < NCHUNK) issue(c + 2);
        else                cp_commit();   // keep wait_group accounting aligned

        const uint32_t as_ = sbase + (((2 * c) / 3) % STAGES) * TILE_B;
        const uint32_t bs_ = sbase + (STAGES + c % STAGES) * TILE_B;

        uint32_t afr[2][4][4], bfr[2][4][4];
        // preload ks=0 fragments
        {
            const int ch = chsel;              // ks=0
#pragma unroll
            for (int mt = 0; mt < 4; mt++)
                ldsm_x4(afr[0][mt], as_ + SWZ((wm * 64 + mt * 16 + rsel) * 128 + ch * 16));
#pragma unroll
            for (int nt = 0; nt < 4; nt++)
                ldsm_x4(bfr[0][nt], bs_ + SWZ((wn * 64 + nt * 16 + rsel) * 128 + ch * 16));
        }

#pragma unroll
        for (int ks = 0; ks < 4; ks++) {
            const int cur = ks & 1;
            const int nxt = cur ^ 1;
            if (ks < 3) {                      // prefetch next ks fragments
                const int ch = (ks + 1) * 2 + chsel;
#pragma unroll
                for (int mt = 0; mt < 4; mt++)
                    ldsm_x4(afr[nxt][mt], as_ + SWZ((wm * 64 + mt * 16 + rsel) * 128 + ch * 16));
#pragma unroll
                for (int nt = 0; nt < 4; nt++)
                    ldsm_x4(bfr[nxt][nt], bs_ + SWZ((wn * 64 + nt * 16 + rsel) * 128 + ch * 16));
            }
#pragma unroll
            for (int mt = 0; mt < 4; mt++)
#pragma unroll
                for (int nt = 0; nt < 4; nt++) {
                    mma_bf16(acc[mt][nt * 2 + 0], afr[cur][mt], bfr[cur][nt][0], bfr[cur][nt][2]);
                    mma_bf16(acc[mt][nt * 2 + 1], afr[cur][mt], bfr[cur][nt][1], bfr[cur][nt][3]);
                }
        }
    }

    // ---- epilogue ----
    const int gid = lane >> 2;
    const int tig = lane & 3;
    const bool is_sb = (n0 < MEM);
    const int ncol0 = n0 + wn * 64;

#pragma unroll
    for (int mt = 0; mt < 4; mt++) {
#pragma unroll
        for (int rh = 0; rh < 2; rh++) {
            const int row = m0 + wm * 64 + mt * 16 + gid + rh * 8;
            float* dst = is_sb ? (g_sb + (size_t)row * MEM + ncol0)
                               : (out  + (size_t)row * MEM + (ncol0 - MEM));
#pragma unroll
            for (int nt8 = 0; nt8 < 8; nt8++) {
                const int col = nt8 * 8 + tig * 2;
                float2 v;
                v.x = acc[mt][nt8][rh * 2 + 0] + __ldg(&bias[ncol0 + col + 0]);
                v.y = acc[mt][nt8][rh * 2 + 1] + __ldg(&bias[ncol0 + col + 1]);
                if (is_sb) {
                    v.x = BIAS_MOD_RANGE * tanhf(v.x * (1.0f / BIAS_MOD_RANGE));
                    v.y = BIAS_MOD_RANGE * tanhf(v.y * (1.0f / BIAS_MOD_RANGE));
                }
                *(float2*)(dst + col) = v;
            }
        }
    }
}

// ---------------------------------------------------------------------------
// Scan: one thread per (b, m) lane; 512 sequential steps.
// Software-pipelined prefetch depth PD=16 (rolling register arrays);
// streaming ld/st hints (no reuse).
// ---------------------------------------------------------------------------
#define PD 16

__global__ __launch_bounds__(256)
void scan_kernel(const float* __restrict__ h0, float* __restrict__ out)
{
    const int idx = blockIdx.x * blockDim.x + threadIdx.x;
    const int b = idx >> 10;
    const int m = idx & (MEM - 1);

    float hf = h0[(size_t)b * MEM + m];
    float hs = h0[(size_t)BB * MEM + (size_t)b * MEM + m];

    const size_t base = (size_t)b * LL * MEM + m;
    const float* __restrict__ sbp = g_sb + base;
    float* __restrict__ op = out + base;

    float sbv[PD], iov[PD];
#pragma unroll
    for (int j = 0; j < PD; j++) {
        sbv[j] = __ldcs(sbp + (size_t)j * MEM);
        iov[j] = __ldcs(op  + (size_t)j * MEM);
    }

#pragma unroll 1
    for (int t = 0; t < LL; t += PD) {
#pragma unroll
        for (int j = 0; j < PD; j++) {
            const float s  = sbv[j];
            const float io = iov[j];

            if (t + PD + j < LL) {
                sbv[j] = __ldcs(sbp + (size_t)(t + PD + j) * MEM);
                iov[j] = __ldcs(op  + (size_t)(t + PD + j) * MEM);
            }

            const float d   = hs + MOD_BIAS;
            const float arg = io + SOMA_FAST * hf - SOMA_SLOW * d * d + s;
            const float hfn = tanhf(arg);

            const float sg  = 1.0f / (1.0f + expf(-10.0f * (hf - 0.5f)));
            const float eps = EPS_BASE + EPS_BASE * sg;
            hs = (1.0f - eps) * hs + eps * hf;
            hf = hfn;

            __stcs(op + (size_t)(t + j) * MEM, hfn);
        }
    }
    out[(size_t)MDIM * MEM + (size_t)b * MEM + m] = hf;
}

// ---------------------------------------------------------------------------
// Launch
// ---------------------------------------------------------------------------
extern "C" void kernel_launch(void* const* d_in, const int* in_sizes, int n_in,
                              void* d_out, int out_size)
{
    const float* u    = (const float*)d_in[0];
    const float* h0   = (const float*)d_in[1];
    const float* W_im = (const float*)d_in[2];
    const float* b_im = (const float*)d_in[3];
    float* out = (float*)d_out;

    cudaFuncSetAttribute(gemm_hmma_kernel,
                         cudaFuncAttributeMaxDynamicSharedMemorySize, GEMM_SMEM);

    split_w_kernel<<<(NDIM * KDIM / 4) / 256, 256>>>(W_im);
    split_a_kernel<<<(MDIM * KDIM / 4) / 256, 256>>>(u);

    dim3 ggrid(NDIM / GBN, MDIM / GBM);  // (16, 512)
    gemm_hmma_kernel<<<ggrid, 128, GEMM_SMEM>>>(b_im, out);

    scan_kernel<<<(BB * MEM) / 256, 256>>>(h0, out);
}